// round 1
// baseline (speedup 1.0000x reference)
#include <cuda_runtime.h>
#include <math.h>

#define N_ROWS 8192
#define F_IN   128
#define F_OUT  64
#define ALPHA  0.2f

// Scratch (device globals — no allocation allowed in kernel_launch)
__device__ float g_Wh[N_ROWS * F_OUT];   // 2 MB, L2-resident
__device__ float g_s[N_ROWS];
__device__ float g_d[N_ROWS];
__device__ float g_dmax;

// ---------------------------------------------------------------------------
// Kernel A: Wh = h @ W ; s = Wh @ a1 ; d = Wh @ a2
// 512 blocks x 128 threads, 16 rows per block.
// ---------------------------------------------------------------------------
__global__ __launch_bounds__(128) void wh_kernel(const float* __restrict__ h,
                                                 const float* __restrict__ W,
                                                 const float* __restrict__ a)
{
    __shared__ float h_sh[16][F_IN];      // 8 KB
    __shared__ float W_sh[F_IN][F_OUT];   // 32 KB
    __shared__ float wh_sh[16][F_OUT];    // 4 KB
    __shared__ float a_sh[2 * F_OUT];

    const int tid = threadIdx.x;
    const int row_base = blockIdx.x * 16;

    // Load W: 2048 float4
    const float4* Wv  = (const float4*)W;
    float4*       Wsv = (float4*)W_sh;
#pragma unroll
    for (int k = 0; k < 16; k++) Wsv[tid + k * 128] = Wv[tid + k * 128];

    // Load h tile: 512 float4
    const float4* hv  = (const float4*)(h + (size_t)row_base * F_IN);
    float4*       hsv = (float4*)h_sh;
#pragma unroll
    for (int k = 0; k < 4; k++) hsv[tid + k * 128] = hv[tid + k * 128];

    a_sh[tid] = a[tid];
    __syncthreads();

    const int c  = tid & 63;     // output column
    const int rh = tid >> 6;     // row half (0/1), 8 rows each

    float acc[8];
#pragma unroll
    for (int r = 0; r < 8; r++) acc[r] = 0.f;

#pragma unroll 8
    for (int k = 0; k < F_IN; k++) {
        float wv = W_sh[k][c];
#pragma unroll
        for (int r = 0; r < 8; r++)
            acc[r] = fmaf(h_sh[rh * 8 + r][k], wv, acc[r]);
    }

#pragma unroll
    for (int r = 0; r < 8; r++) {
        wh_sh[rh * 8 + r][c] = acc[r];
        g_Wh[(size_t)(row_base + rh * 8 + r) * F_OUT + c] = acc[r];
    }
    __syncthreads();

    if (tid < 16) {
        float sv = 0.f, dv = 0.f;
#pragma unroll
        for (int cc = 0; cc < F_OUT; cc++) {
            float v = wh_sh[tid][cc];
            sv = fmaf(v, a_sh[cc], sv);
            dv = fmaf(v, a_sh[F_OUT + cc], dv);
        }
        g_s[row_base + tid] = sv;
        g_d[row_base + tid] = dv;
    }
}

// ---------------------------------------------------------------------------
// Kernel B: dmax = max_j d_j  (single block reduce)
// ---------------------------------------------------------------------------
__global__ __launch_bounds__(256) void dmax_kernel()
{
    __shared__ float red[256];
    const int tid = threadIdx.x;
    float m = -1e30f;
    for (int i = tid; i < N_ROWS; i += 256) m = fmaxf(m, g_d[i]);
    red[tid] = m;
    __syncthreads();
#pragma unroll
    for (int s = 128; s > 0; s >>= 1) {
        if (tid < s) red[tid] = fmaxf(red[tid], red[tid + s]);
        __syncthreads();
    }
    if (tid == 0) g_dmax = red[0];
}

// ---------------------------------------------------------------------------
// Kernel C: flash-style softmax(lrelu(s_i + d_j)) @ Wh, then ELU.
// 128 blocks x 128 threads; 64 rows/block; j processed in 64-wide tiles.
// Thread tile: 4 rows x 8 cols (32 fp32 accumulators).
// Row max is analytic: m_i = lrelu(s_i + dmax)  (lrelu monotone).
// ---------------------------------------------------------------------------
__global__ __launch_bounds__(128) void attn_kernel(float* __restrict__ out)
{
    __shared__ float wh_sh[64][F_OUT];   // 16 KB
    __shared__ float w_sh[64][64];       // 16 KB  (w_sh[jj][i])
    __shared__ float zsh[128];
    __shared__ float rinv_sh[64];

    const int tid  = threadIdx.x;
    const int row0 = blockIdx.x * 64;

    // phase-A identity: this thread owns softmax row i (two threads per row)
    const int i    = tid & 63;
    const int half = tid >> 6;
    const float s_i  = g_s[row0 + i];
    const float dmax = g_dmax;
    const float xm   = s_i + dmax;
    const float m_i  = fmaxf(xm, ALPHA * xm);   // lrelu(s_i + dmax)

    // phase-B identity: 4 rows x 8 cols
    const int cg = tid & 7;
    const int rg = tid >> 3;      // 0..15
    const int r0 = rg * 4;
    const int c0 = cg * 8;

    float acc[4][8];
#pragma unroll
    for (int r = 0; r < 4; r++)
#pragma unroll
        for (int cc = 0; cc < 8; cc++) acc[r][cc] = 0.f;

    float zacc = 0.f;

    for (int j0 = 0; j0 < N_ROWS; j0 += 64) {
        __syncthreads();   // previous phase B done with smem

        // Stage Wh tile (64x64) into registers from L2
        float4 v[8];
        const float4* gv = (const float4*)(g_Wh + (size_t)j0 * F_OUT);
#pragma unroll
        for (int k = 0; k < 8; k++) v[k] = gv[tid + k * 128];

        // Phase A: softmax weights for this tile (each thread: 32 j's, row i)
#pragma unroll 8
        for (int jj = 0; jj < 32; jj++) {
            int j = half * 32 + jj;
            float x  = s_i + g_d[j0 + j];
            float lr = fmaxf(x, ALPHA * x);
            float e  = __expf(lr - m_i);
            w_sh[j][i] = e;
            zacc += e;
        }

        // Commit Wh tile to smem
        float4* wsv = (float4*)wh_sh;
#pragma unroll
        for (int k = 0; k < 8; k++) wsv[tid + k * 128] = v[k];
        __syncthreads();

        // Phase B: acc[i][c] += w[j][i] * Wh[j][c]
#pragma unroll 8
        for (int jj = 0; jj < 64; jj++) {
            float4 w4 = *(const float4*)(&w_sh[jj][r0]);
            float4 p  = *(const float4*)(&wh_sh[jj][c0]);
            float4 q  = *(const float4*)(&wh_sh[jj][c0 + 4]);
            float wv[4] = {w4.x, w4.y, w4.z, w4.w};
            float pv[8] = {p.x, p.y, p.z, p.w, q.x, q.y, q.z, q.w};
#pragma unroll
            for (int r = 0; r < 4; r++)
#pragma unroll
                for (int cc = 0; cc < 8; cc++)
                    acc[r][cc] = fmaf(wv[r], pv[cc], acc[r][cc]);
        }
    }

    // Reduce Z per row (2 partials), invert once
    zsh[tid] = zacc;
    __syncthreads();
    if (tid < 64) rinv_sh[tid] = 1.f / (zsh[tid] + zsh[tid + 64]);
    __syncthreads();

    // Normalize + ELU + store
#pragma unroll
    for (int r = 0; r < 4; r++) {
        float rv = rinv_sh[r0 + r];
#pragma unroll
        for (int cc = 0; cc < 8; cc++) {
            float val = acc[r][cc] * rv;
            out[(size_t)(row0 + r0 + r) * F_OUT + c0 + cc] =
                (val > 0.f) ? val : expm1f(val);
        }
    }
}

// ---------------------------------------------------------------------------
extern "C" void kernel_launch(void* const* d_in, const int* in_sizes, int n_in,
                              void* d_out, int out_size)
{
    const float* h = (const float*)d_in[0];
    const float* W = (const float*)d_in[1];
    const float* a = (const float*)d_in[2];
    float* out = (float*)d_out;

    wh_kernel<<<N_ROWS / 16, 128>>>(h, W, a);
    dmax_kernel<<<1, 256>>>();
    attn_kernel<<<N_ROWS / 64, 128>>>(out);
}

// round 2
// speedup vs baseline: 4.1726x; 4.1726x over previous
#include <cuda_runtime.h>
#include <math.h>

#define NR    8192
#define F_IN  128
#define F_OUT 64
#define ALPHA 0.2f
#define LDW   68          // padded row stride (65 used) for scan arrays
#define NSEG  64          // 8192 / 128
#define SEGSZ 128

// ---------------- scratch (device globals; no allocs allowed) ----------------
__device__ float g_Wh[NR * F_OUT];        // 2 MB
__device__ float g_s[NR];
__device__ float g_d[NR];
__device__ float g_dmax;
__device__ unsigned long long g_key[NR];  // sortable key (d bits || index)
__device__ int   g_rank[NR];
__device__ float g_dsort[NR];
__device__ int   g_idx[NR];
__device__ float g_locPre[NR * LDW];      // D-weighted exclusive prefix (within segment)
__device__ float g_locSuf[NR * LDW];      // B-weighted inclusive suffix (within segment)
__device__ float g_segPre[NSEG * LDW];
__device__ float g_segSuf[NSEG * LDW];
__device__ float g_offPre[(NSEG + 1) * LDW]; // sum of segments before g (g=64 -> grand total)
__device__ float g_offSuf[NSEG * LDW];       // sum of segments after g

// ---------------------------------------------------------------------------
// Kernel A: Wh = h @ W ; s = Wh @ a1 ; d = Wh @ a2
// ---------------------------------------------------------------------------
__global__ __launch_bounds__(128) void wh_kernel(const float* __restrict__ h,
                                                 const float* __restrict__ W,
                                                 const float* __restrict__ a)
{
    __shared__ float h_sh[16][F_IN];
    __shared__ float W_sh[F_IN][F_OUT];
    __shared__ float wh_sh[16][F_OUT];
    __shared__ float a_sh[2 * F_OUT];

    const int tid = threadIdx.x;
    const int row_base = blockIdx.x * 16;

    const float4* Wv  = (const float4*)W;
    float4*       Wsv = (float4*)W_sh;
#pragma unroll
    for (int k = 0; k < 16; k++) Wsv[tid + k * 128] = Wv[tid + k * 128];

    const float4* hv  = (const float4*)(h + (size_t)row_base * F_IN);
    float4*       hsv = (float4*)h_sh;
#pragma unroll
    for (int k = 0; k < 4; k++) hsv[tid + k * 128] = hv[tid + k * 128];

    a_sh[tid] = a[tid];
    __syncthreads();

    const int c  = tid & 63;
    const int rh = tid >> 6;

    float acc[8];
#pragma unroll
    for (int r = 0; r < 8; r++) acc[r] = 0.f;

#pragma unroll 8
    for (int k = 0; k < F_IN; k++) {
        float wv = W_sh[k][c];
#pragma unroll
        for (int r = 0; r < 8; r++)
            acc[r] = fmaf(h_sh[rh * 8 + r][k], wv, acc[r]);
    }

#pragma unroll
    for (int r = 0; r < 8; r++) {
        wh_sh[rh * 8 + r][c] = acc[r];
        g_Wh[(size_t)(row_base + rh * 8 + r) * F_OUT + c] = acc[r];
    }
    __syncthreads();

    if (tid < 16) {
        float sv = 0.f, dv = 0.f;
#pragma unroll
        for (int cc = 0; cc < F_OUT; cc++) {
            float v = wh_sh[tid][cc];
            sv = fmaf(v, a_sh[cc], sv);
            dv = fmaf(v, a_sh[F_OUT + cc], dv);
        }
        g_s[row_base + tid] = sv;
        g_d[row_base + tid] = dv;
    }
}

// ---------------------------------------------------------------------------
// Kernel B: dmax = max_j d_j
// ---------------------------------------------------------------------------
__global__ __launch_bounds__(256) void dmax_kernel()
{
    __shared__ float red[256];
    const int tid = threadIdx.x;
    float m = -1e30f;
    for (int i = tid; i < NR; i += 256) m = fmaxf(m, g_d[i]);
    red[tid] = m;
    __syncthreads();
#pragma unroll
    for (int s = 128; s > 0; s >>= 1) {
        if (tid < s) red[tid] = fmaxf(red[tid], red[tid + s]);
        __syncthreads();
    }
    if (tid == 0) g_dmax = red[0];
}

// ---------------------------------------------------------------------------
// Kernel P: pack sortable 64-bit keys (ascending float order, index tiebreak)
// ---------------------------------------------------------------------------
__global__ __launch_bounds__(256) void pack_kernel()
{
    int j = blockIdx.x * 256 + threadIdx.x;
    unsigned u = __float_as_uint(g_d[j]);
    u ^= (u & 0x80000000u) ? 0xFFFFFFFFu : 0x80000000u;
    g_key[j] = ((unsigned long long)u << 13) | (unsigned)j;
    g_rank[j] = 0;
}

// ---------------------------------------------------------------------------
// Kernel R: rank by counting. Block (jb,q) counts keys in quarter q below the
// keys of j-chunk jb. smem reads are warp-uniform (broadcast).
// ---------------------------------------------------------------------------
__global__ __launch_bounds__(128) void rank_kernel()
{
    __shared__ unsigned long long ksh[2048];
    const int jb = blockIdx.x >> 2;
    const int q  = blockIdx.x & 3;
    const int t  = threadIdx.x;
    const int j  = jb * 128 + t;
    const unsigned long long mykey = g_key[j];

    const int base = q * 2048;
    for (int i = t; i < 2048; i += 128) ksh[i] = g_key[base + i];
    __syncthreads();

    int cnt = 0;
#pragma unroll 8
    for (int k = 0; k < 2048; k++) cnt += (ksh[k] < mykey);

    atomicAdd(&g_rank[j], cnt);
}

// ---------------------------------------------------------------------------
// Kernel Sc: scatter into sorted order
// ---------------------------------------------------------------------------
__global__ __launch_bounds__(256) void scatter_kernel()
{
    int j = blockIdx.x * 256 + threadIdx.x;
    int r = g_rank[j];
    g_dsort[r] = g_d[j];
    g_idx[r]   = j;
}

// ---------------------------------------------------------------------------
// Kernel S1: per-segment scans of D*[Wh|1] (prefix, exclusive) and
// B*[Wh|1] (suffix, inclusive), segment = 128 sorted positions.
// ---------------------------------------------------------------------------
__global__ __launch_bounds__(128) void scan_kernel()
{
    __shared__ float wh[SEGSZ][65];   // padded to kill bank conflicts
    __shared__ float Bsh[SEGSZ], Dsh[SEGSZ];

    const int g = blockIdx.x;
    const int t = threadIdx.x;
    const int base = g * SEGSZ;

    // gather Wh row of sorted position base+t
    const int src = g_idx[base + t];
    const float4* wr = (const float4*)(g_Wh + (size_t)src * F_OUT);
#pragma unroll
    for (int i = 0; i < 16; i++) {
        float4 v = wr[i];
        wh[t][i * 4 + 0] = v.x;
        wh[t][i * 4 + 1] = v.y;
        wh[t][i * 4 + 2] = v.z;
        wh[t][i * 4 + 3] = v.w;
    }
    const float dm = g_dmax;
    const float dv = g_dsort[base + t];
    Bsh[t] = __expf(dv - dm);
    Dsh[t] = __expf(ALPHA * (dv - dm));
    __syncthreads();

    if (t < 65) {
        // D-weighted exclusive prefix
        float acc = 0.f;
        for (int k = 0; k < SEGSZ; k++) {
            g_locPre[(size_t)(base + k) * LDW + t] = acc;
            float x = (t < 64) ? wh[k][t] : 1.f;
            acc = fmaf(Dsh[k], x, acc);
        }
        g_segPre[g * LDW + t] = acc;

        // B-weighted inclusive suffix
        float acc2 = 0.f;
        for (int k = SEGSZ - 1; k >= 0; k--) {
            float x = (t < 64) ? wh[k][t] : 1.f;
            acc2 = fmaf(Bsh[k], x, acc2);
            g_locSuf[(size_t)(base + k) * LDW + t] = acc2;
        }
        g_segSuf[g * LDW + t] = acc2;
    }
}

// ---------------------------------------------------------------------------
// Kernel S2: scan segment totals into offsets (1 block)
// ---------------------------------------------------------------------------
__global__ __launch_bounds__(128) void segscan_kernel()
{
    const int t = threadIdx.x;
    if (t >= 65) return;
    float acc = 0.f;
    for (int g = 0; g < NSEG; g++) {
        g_offPre[g * LDW + t] = acc;
        acc += g_segPre[g * LDW + t];
    }
    g_offPre[NSEG * LDW + t] = acc;   // grand total (t == 8192 case)

    float acc2 = 0.f;
    for (int g = NSEG - 1; g >= 0; g--) {
        g_offSuf[g * LDW + t] = acc2; // sum of segments strictly after g
        acc2 += g_segSuf[g * LDW + t];
    }
}

// ---------------------------------------------------------------------------
// Kernel F: per-row combine: binary search split, numerator = A*suf + C*pre,
// normalize, ELU.
// ---------------------------------------------------------------------------
__global__ __launch_bounds__(128) void final_kernel(float* __restrict__ out)
{
    __shared__ float dsh[NR];   // 32 KB sorted keys
    const int t = threadIdx.x;
    for (int i = t; i < NR; i += 128) dsh[i] = g_dsort[i];
    __syncthreads();

    const int i = blockIdx.x * 128 + t;
    const float s  = g_s[i];
    const float dm = g_dmax;
    const float xm = s + dm;
    const float m  = fmaxf(xm, ALPHA * xm);          // lrelu(s_i + dmax)
    const float A  = __expf(s + dm - m);             // branch x>0 row factor
    const float C  = __expf(ALPHA * (s + dm) - m);   // branch x<=0 row factor
    const float th = -s;

    // upper_bound: count of d_j <= -s_i
    int lo = 0, hi = NR;
    while (lo < hi) {
        int mid = (lo + hi) >> 1;
        if (dsh[mid] <= th) lo = mid + 1; else hi = mid;
    }
    const int tpos = lo;                 // 0..8192
    const bool full = (tpos == NR);
    const int  g    = full ? 0 : (tpos >> 7);

    const float* offP = g_offPre + (full ? NSEG : g) * LDW;
    const float* offS = g_offSuf + g * LDW;
    const float* locP = g_locPre + (size_t)(full ? 0 : tpos) * LDW;
    const float* locS = g_locSuf + (size_t)(full ? 0 : tpos) * LDW;

    // Z from scalar column (65th)
    float preZ = offP[64] + (full ? 0.f : locP[64]);
    float sufZ = full ? 0.f : (offS[64] + locS[64]);
    float Z  = fmaf(A, sufZ, C * preZ);
    float rz = 1.f / Z;

    float* op = out + (size_t)i * F_OUT;
#pragma unroll 8
    for (int c = 0; c < F_OUT; c++) {
        float pre = offP[c] + (full ? 0.f : locP[c]);
        float suf = full ? 0.f : (offS[c] + locS[c]);
        float v = fmaf(A, suf, C * pre) * rz;
        op[c] = (v > 0.f) ? v : expm1f(v);
    }
}

// ---------------------------------------------------------------------------
extern "C" void kernel_launch(void* const* d_in, const int* in_sizes, int n_in,
                              void* d_out, int out_size)
{
    const float* h = (const float*)d_in[0];
    const float* W = (const float*)d_in[1];
    const float* a = (const float*)d_in[2];
    float* out = (float*)d_out;

    wh_kernel<<<NR / 16, 128>>>(h, W, a);
    dmax_kernel<<<1, 256>>>();
    pack_kernel<<<NR / 256, 256>>>();
    rank_kernel<<<NSEG * 4, 128>>>();
    scatter_kernel<<<NR / 256, 256>>>();
    scan_kernel<<<NSEG, 128>>>();
    segscan_kernel<<<1, 128>>>();
    final_kernel<<<NR / 128, 128>>>(out);
}